// round 2
// baseline (speedup 1.0000x reference)
#include <cuda_runtime.h>
#include <math.h>

#define BB 64
#define TT 1024
#define CC 512

// device-global scratch (no allocations allowed)
__device__ float4 g_lp[BB * TT];  // top-4 log-probs per (b,t), value-desc
__device__ int4   g_tc[BB * TT];  // their class ids

// ---------------------------------------------------------------------------
// Kernel A: one warp per (b,t) row of 512 logits.
//   M  = row max (exact, order-free)
//   L  = log(sum(exp(x-M))): fp32 exp terms (matches XLA elementwise exp arg
//        bitwise), summed EXACTLY in double, double log -> fp32. This is the
//        only scalar whose rounding matters for tie replication.
//   lp_k = fl32(fl32(x_k - M) - L) for the top-4 classes (min-class tie order)
// ---------------------------------------------------------------------------
__global__ __launch_bounds__(256) void row_topk_kernel(const float* __restrict__ logits) {
    int gwarp = (blockIdx.x * blockDim.x + threadIdx.x) >> 5;
    int lane  = threadIdx.x & 31;
    if (gwarp >= BB * TT) return;

    const float4* row = reinterpret_cast<const float4*>(logits + (size_t)gwarp * CC);
    float x[16];
#pragma unroll
    for (int i = 0; i < 4; i++) {
        float4 v = row[lane + 32 * i];  // coalesced
        x[4*i+0] = v.x; x[4*i+1] = v.y; x[4*i+2] = v.z; x[4*i+3] = v.w;
    }

    // row max
    float M = x[0];
#pragma unroll
    for (int s = 1; s < 16; s++) M = fmaxf(M, x[s]);
#pragma unroll
    for (int off = 16; off > 0; off >>= 1)
        M = fmaxf(M, __shfl_xor_sync(0xffffffffu, M, off));

    // top-4 by value (desc), class asc on equal values; masked passes
    unsigned sel = 0u;
    float tv[4]; int tc[4];
#pragma unroll
    for (int k = 0; k < 4; k++) {
        float bv = -3.4e38f; int bc = 0x7fffffff;
#pragma unroll
        for (int i = 0; i < 4; i++)
#pragma unroll
            for (int j = 0; j < 4; j++) {
                int slot = i * 4 + j;
                if (!((sel >> slot) & 1u)) {
                    float xv = x[slot];                 // class ascending in (i,j)
                    if (xv > bv) { bv = xv; bc = 128 * i + 4 * lane + j; }
                }
            }
#pragma unroll
        for (int off = 16; off > 0; off >>= 1) {
            float ov = __shfl_xor_sync(0xffffffffu, bv, off);
            int   oc = __shfl_xor_sync(0xffffffffu, bc, off);
            if (ov > bv || (ov == bv && oc < bc)) { bv = ov; bc = oc; }
        }
        tv[k] = bv; tc[k] = bc;
        if (((bc >> 2) & 31) == lane) {                 // owner lane masks slot
            int i = bc >> 7, j = bc & 3;
            sel |= 1u << (i * 4 + j);
        }
    }

    // exact-sum logsumexp
    double S = 0.0;
#pragma unroll
    for (int s = 0; s < 16; s++) S += (double)__expf(x[s] - M);
#pragma unroll
    for (int off = 16; off > 0; off >>= 1)
        S += __shfl_xor_sync(0xffffffffu, S, off);

    if (lane == 0) {
        float L = (float)log(S);
        float4 lp;
        lp.x = __fadd_rn(__fadd_rn(tv[0], -M), -L);
        lp.y = __fadd_rn(__fadd_rn(tv[1], -M), -L);
        lp.z = __fadd_rn(__fadd_rn(tv[2], -M), -L);
        lp.w = __fadd_rn(__fadd_rn(tv[3], -M), -L);
        g_lp[gwarp] = lp;
        g_tc[gwarp] = make_int4(tc[0], tc[1], tc[2], tc[3]);
    }
}

// ---------------------------------------------------------------------------
// Kernel B: one 32-thread block per batch.
//  lane 0: exact fp32 scan replication with tie rule
//     r = fl(s + lp1); chosen = min class among {k: fl(s+lp_k)==r}; s = r
//  whole warp: CTC collapse (keep t iff cls!=BLANK and cls != prev non-blank),
//  left-compacted, -1 padded; lengths; scores[:,0].
// ---------------------------------------------------------------------------
__global__ __launch_bounds__(32) void scan_decode_kernel(float* __restrict__ out_f,
                                                         int* __restrict__ out_i,
                                                         int mode) {
    int b    = blockIdx.x;
    int lane = threadIdx.x;

    __shared__ int   scls[TT];
    __shared__ float sscore;

    if (lane == 0) {
        float s = 0.0f;
#pragma unroll 4
        for (int t = 0; t < TT; t++) {
            float4 lp = g_lp[b * TT + t];
            int4   c  = g_tc[b * TT + t];
            float r = __fadd_rn(s, lp.x);
            int  ch = c.x;
            if (__fadd_rn(s, lp.y) == r && c.y < ch) ch = c.y;
            if (__fadd_rn(s, lp.z) == r && c.z < ch) ch = c.z;
            if (__fadd_rn(s, lp.w) == r && c.w < ch) ch = c.w;
            scls[t] = ch;
            s = r;
        }
        sscore = s;
    }
    __syncwarp();

    // prefill decoded row with -1
    for (int t = lane; t < TT; t += 32) {
        if (mode == 0) out_f[b * TT + t] = -1.0f;
        else           out_i[b * TT + t] = -1;
    }
    __syncwarp();

    // ballot collapse, 32 chunks of 32
    int carryCnt  = 0;
    int carryPrev = -1;
    for (int chunk = 0; chunk < TT / 32; chunk++) {
        int t   = chunk * 32 + lane;
        int cls = scls[t];
        bool nb = (cls != 0);

        unsigned nbm   = __ballot_sync(0xffffffffu, nb);
        unsigned lmask = (lane == 0) ? 0u : (0xffffffffu >> (32 - lane));
        unsigned below = nbm & lmask;
        int src = 31 - __clz(below);                    // -1 if none
        int pc  = __shfl_sync(0xffffffffu, cls, src & 31);
        int myPrev = below ? pc : carryPrev;

        bool keep = nb && (cls != myPrev);
        unsigned km = __ballot_sync(0xffffffffu, keep);
        int dst = carryCnt + __popc(km & lmask);
        if (keep) {
            if (mode == 0) out_f[b * TT + dst] = (float)cls;
            else           out_i[b * TT + dst] = cls;
        }
        carryCnt += __popc(km);
        if (nbm) carryPrev = __shfl_sync(0xffffffffu, cls, 31 - __clz(nbm));
    }

    if (lane == 0 && mode == 0) {
        out_f[BB * TT + b]      = (float)carryCnt;  // lengths
        out_f[BB * TT + BB + b] = sscore;           // scores[:,0]
    }
}

extern "C" void kernel_launch(void* const* d_in, const int* in_sizes, int n_in,
                              void* d_out, int out_size) {
    const float* logits = (const float*)d_in[0];

    row_topk_kernel<<<(BB * TT) / 8, 256>>>(logits);

    int mode = (out_size == BB * TT) ? 1 : 0;
    scan_decode_kernel<<<BB, 32>>>((float*)d_out, (int*)d_out, mode);
}

// round 3
// speedup vs baseline: 6.4728x; 6.4728x over previous
#include <cuda_runtime.h>
#include <math.h>

#define BB 64
#define TT 1024
#define CC 512
#define TIE_W 1e-3f   // covers max fp32 ulp of |score|<6400 (<=4.88e-4) + lp rounding

// device scratch
__device__ float2 g_m[BB * TT];    // .x = lp1 (= -L), .y = int bits: cls | (tie?1<<30)
__device__ float4 g_lp4[BB * TT];  // tie rows only: top-4 lp (desc)
__device__ int4   g_c4[BB * TT];   // tie rows only: top-4 classes

// ---------------------------------------------------------------------------
// Kernel A: one warp per (b,t) row of 512 logits. FP32 only.
//   M = row max, c1 = argmax (min class on ties)
//   L = log(sum exp(x-M)) via compensated fp32 sum + logf (abs err ~5e-7)
//   If >=2 classes within TIE_W of M (rare): emit top-4 (lp, class) sidecar.
// ---------------------------------------------------------------------------
__global__ __launch_bounds__(256) void row_kernel(const float* __restrict__ logits) {
    int gwarp = (blockIdx.x * blockDim.x + threadIdx.x) >> 5;
    int lane  = threadIdx.x & 31;
    if (gwarp >= BB * TT) return;

    const float4* row = reinterpret_cast<const float4*>(logits + (size_t)gwarp * CC);
    float x[16];
#pragma unroll
    for (int i = 0; i < 4; i++) {
        float4 v = row[lane + 32 * i];  // coalesced
        x[4*i+0] = v.x; x[4*i+1] = v.y; x[4*i+2] = v.z; x[4*i+3] = v.w;
    }

    // ---- max + argmax (class ascending within lane; min class cross-lane) ----
    float m = x[0];
    int   mc = 4 * lane;                    // class of slot (i=0,j=0)
#pragma unroll
    for (int i = 0; i < 4; i++)
#pragma unroll
        for (int j = 0; j < 4; j++) {
            if (i == 0 && j == 0) continue;
            float xv = x[4*i+j];
            if (xv > m) { m = xv; mc = 128*i + 4*lane + j; }
        }
#pragma unroll
    for (int off = 16; off > 0; off >>= 1) {
        float om = __shfl_xor_sync(0xffffffffu, m, off);
        int   oc = __shfl_xor_sync(0xffffffffu, mc, off);
        if (om > m || (om == m && oc < mc)) { m = om; mc = oc; }
    }
    float M = m;   // all lanes agree
    int   c1 = mc;

    // ---- compensated fp32 sum of exp(x - M) ----
    float s = 0.0f, c = 0.0f;               // value = s + c (Kahan per lane)
#pragma unroll
    for (int k = 0; k < 16; k++) {
        float y = __expf(x[k] - M) - c;
        float t = s + y;
        c = (t - s) - y;
        s = t;
    }
    c = -c;                                  // now value = s + c
#pragma unroll
    for (int off = 16; off > 0; off >>= 1) {
        float os = __shfl_xor_sync(0xffffffffu, s, off);
        float oc = __shfl_xor_sync(0xffffffffu, c, off);
        // TwoSum(s, os)
        float t = s + os;
        float z = t - s;
        float e = (s - (t - z)) + (os - z);
        c = c + oc + e;
        s = t;
    }
    float L = logf(s) + c / s;               // ~1-2 ulp fp32 log, identical all lanes

    // ---- tie window count ----
    float thr = M - TIE_W;
    int cnt = 0;
#pragma unroll
    for (int k = 0; k < 16; k++) cnt += (x[k] >= thr);
#pragma unroll
    for (int off = 16; off > 0; off >>= 1)
        cnt += __shfl_xor_sync(0xffffffffu, cnt, off);

    if (cnt < 2) {                           // fast path (overwhelming majority)
        if (lane == 0)
            g_m[gwarp] = make_float2(-L, __int_as_float(c1));
        return;
    }

    // ---- rare tie path: full masked top-4 ----
    unsigned sel = 0u;
    float tv[4]; int tc[4];
#pragma unroll
    for (int k = 0; k < 4; k++) {
        float bv = -3.4e38f; int bc = 0x7fffffff;
#pragma unroll
        for (int i = 0; i < 4; i++)
#pragma unroll
            for (int j = 0; j < 4; j++) {
                int slot = i * 4 + j;
                if (!((sel >> slot) & 1u)) {
                    float xv = x[slot];
                    if (xv > bv) { bv = xv; bc = 128*i + 4*lane + j; }
                }
            }
#pragma unroll
        for (int off = 16; off > 0; off >>= 1) {
            float ov = __shfl_xor_sync(0xffffffffu, bv, off);
            int   oc = __shfl_xor_sync(0xffffffffu, bc, off);
            if (ov > bv || (ov == bv && oc < bc)) { bv = ov; bc = oc; }
        }
        tv[k] = bv; tc[k] = bc;
        if (((bc >> 2) & 31) == lane) {
            int i = bc >> 7, j = bc & 3;
            sel |= 1u << (i * 4 + j);
        }
    }
    if (lane == 0) {
        float4 lp;
        lp.x = -L;                                          // tv[0] == M
        lp.y = __fadd_rn(__fadd_rn(tv[1], -M), -L);
        lp.z = __fadd_rn(__fadd_rn(tv[2], -M), -L);
        lp.w = __fadd_rn(__fadd_rn(tv[3], -M), -L);
        g_lp4[gwarp] = lp;
        g_c4[gwarp]  = make_int4(tc[0], tc[1], tc[2], tc[3]);
        g_m[gwarp]   = make_float2(-L, __int_as_float(c1 | (1 << 30)));
    }
}

// ---------------------------------------------------------------------------
// Kernel B: one block (256 thr) per batch.
//  stage lp/cls to shared -> thread 0 fp32 prefix chain -> parallel tie
//  resolution -> warp-0 ballot CTC collapse -> outputs.
// ---------------------------------------------------------------------------
__global__ __launch_bounds__(256) void scan_decode_kernel(float* __restrict__ out_f,
                                                          int* __restrict__ out_i,
                                                          int mode) {
    int b    = blockIdx.x;
    int tid  = threadIdx.x;
    int lane = tid & 31;

    __shared__ float s_lp[TT];
    __shared__ int   s_cls[TT];
    __shared__ float s_pref[TT];
    __shared__ float s_score;

    // stage + prefill output row with -1
#pragma unroll
    for (int k = 0; k < TT / 256; k++) {
        int t = tid + 256 * k;
        float2 mrec = g_m[b * TT + t];
        s_lp[t]  = mrec.x;
        s_cls[t] = __float_as_int(mrec.y);
        if (mode == 0) out_f[b * TT + t] = -1.0f;
        else           out_i[b * TT + t] = -1;
    }
    __syncthreads();

    // sequential fp32 prefix (exact scan replication), from shared
    if (tid == 0) {
        float s = 0.0f;
#pragma unroll 8
        for (int t = 0; t < TT; t++) {
            s_pref[t] = s;
            s = __fadd_rn(s, s_lp[t]);
        }
        s_score = s;
    }
    __syncthreads();

    // tie resolution (parallel; flagged rows are rare)
#pragma unroll
    for (int k = 0; k < TT / 256; k++) {
        int t = tid + 256 * k;
        int v = s_cls[t];
        if (v & (1 << 30)) {
            float4 lp = g_lp4[b * TT + t];
            int4   cc = g_c4[b * TT + t];
            float  s  = s_pref[t];
            float  r  = __fadd_rn(s, lp.x);
            int ch = cc.x;
            if (__fadd_rn(s, lp.y) == r && cc.y < ch) ch = cc.y;
            if (__fadd_rn(s, lp.z) == r && cc.z < ch) ch = cc.z;
            if (__fadd_rn(s, lp.w) == r && cc.w < ch) ch = cc.w;
            s_cls[t] = ch;
        }
    }
    __syncthreads();

    // warp 0: ballot CTC collapse over shared classes
    if (tid < 32) {
        int carryCnt  = 0;
        int carryPrev = -1;
        unsigned lmask = (lane == 0) ? 0u : (0xffffffffu >> (32 - lane));
        for (int chunk = 0; chunk < TT / 32; chunk++) {
            int t   = chunk * 32 + lane;
            int cls = s_cls[t];
            bool nb = (cls != 0);

            unsigned nbm   = __ballot_sync(0xffffffffu, nb);
            unsigned below = nbm & lmask;
            int src = 31 - __clz(below);
            int pc  = __shfl_sync(0xffffffffu, cls, src & 31);
            int myPrev = below ? pc : carryPrev;

            bool keep = nb && (cls != myPrev);
            unsigned km = __ballot_sync(0xffffffffu, keep);
            int dst = carryCnt + __popc(km & lmask);
            if (keep) {
                if (mode == 0) out_f[b * TT + dst] = (float)cls;
                else           out_i[b * TT + dst] = cls;
            }
            carryCnt += __popc(km);
            if (nbm) carryPrev = __shfl_sync(0xffffffffu, cls, 31 - __clz(nbm));
        }
        if (lane == 0 && mode == 0) {
            out_f[BB * TT + b]      = (float)carryCnt;  // lengths
            out_f[BB * TT + BB + b] = s_score;          // scores[:,0]
        }
    }
}

extern "C" void kernel_launch(void* const* d_in, const int* in_sizes, int n_in,
                              void* d_out, int out_size) {
    const float* logits = (const float*)d_in[0];

    row_kernel<<<(BB * TT) / 8, 256>>>(logits);

    int mode = (out_size == BB * TT) ? 1 : 0;
    scan_decode_kernel<<<BB, 256>>>((float*)d_out, (int*)d_out, mode);
}

// round 4
// speedup vs baseline: 8.5828x; 1.3260x over previous
#include <cuda_runtime.h>
#include <math.h>

#define BB 64
#define TT 1024
#define CC 512
#define TIE_W 1e-3f   // covers max fp32 ulp of |score|<6400 (<=4.88e-4) + lp rounding

// device scratch
__device__ float2 g_m[BB * TT];    // .x = lp1 (= -L), .y = int bits: cls | (tie?1<<30)
__device__ float4 g_lp4[BB * TT];  // tie rows only: top-4 lp (desc)
__device__ int4   g_c4[BB * TT];   // tie rows only: top-4 classes

// ---------------------------------------------------------------------------
// Kernel A: one warp per (b,t) row of 512 logits. FP32 only.
// ---------------------------------------------------------------------------
__global__ __launch_bounds__(256) void row_kernel(const float* __restrict__ logits) {
    int gwarp = (blockIdx.x * blockDim.x + threadIdx.x) >> 5;
    int lane  = threadIdx.x & 31;
    if (gwarp >= BB * TT) return;

    const float4* row = reinterpret_cast<const float4*>(logits + (size_t)gwarp * CC);
    float x[16];
#pragma unroll
    for (int i = 0; i < 4; i++) {
        float4 v = row[lane + 32 * i];  // coalesced
        x[4*i+0] = v.x; x[4*i+1] = v.y; x[4*i+2] = v.z; x[4*i+3] = v.w;
    }

    // ---- max + argmax (min class on ties) ----
    float m = x[0];
    int   mc = 4 * lane;
#pragma unroll
    for (int i = 0; i < 4; i++)
#pragma unroll
        for (int j = 0; j < 4; j++) {
            if (i == 0 && j == 0) continue;
            float xv = x[4*i+j];
            if (xv > m) { m = xv; mc = 128*i + 4*lane + j; }
        }
#pragma unroll
    for (int off = 16; off > 0; off >>= 1) {
        float om = __shfl_xor_sync(0xffffffffu, m, off);
        int   oc = __shfl_xor_sync(0xffffffffu, mc, off);
        if (om > m || (om == m && oc < mc)) { m = om; mc = oc; }
    }
    float M = m;
    int   c1 = mc;

    // ---- compensated fp32 sum of exp(x - M) ----
    float s = 0.0f, c = 0.0f;
#pragma unroll
    for (int k = 0; k < 16; k++) {
        float y = __expf(x[k] - M) - c;
        float t = s + y;
        c = (t - s) - y;
        s = t;
    }
    c = -c;
#pragma unroll
    for (int off = 16; off > 0; off >>= 1) {
        float os = __shfl_xor_sync(0xffffffffu, s, off);
        float oc = __shfl_xor_sync(0xffffffffu, c, off);
        float t = s + os;
        float z = t - s;
        float e = (s - (t - z)) + (os - z);
        c = c + oc + e;
        s = t;
    }
    float L = logf(s) + c / s;

    // ---- tie window count ----
    float thr = M - TIE_W;
    int cnt = 0;
#pragma unroll
    for (int k = 0; k < 16; k++) cnt += (x[k] >= thr);
#pragma unroll
    for (int off = 16; off > 0; off >>= 1)
        cnt += __shfl_xor_sync(0xffffffffu, cnt, off);

    if (cnt < 2) {
        if (lane == 0)
            g_m[gwarp] = make_float2(-L, __int_as_float(c1));
        return;
    }

    // ---- rare tie path: full masked top-4 ----
    unsigned sel = 0u;
    float tv[4]; int tc[4];
#pragma unroll
    for (int k = 0; k < 4; k++) {
        float bv = -3.4e38f; int bc = 0x7fffffff;
#pragma unroll
        for (int i = 0; i < 4; i++)
#pragma unroll
            for (int j = 0; j < 4; j++) {
                int slot = i * 4 + j;
                if (!((sel >> slot) & 1u)) {
                    float xv = x[slot];
                    if (xv > bv) { bv = xv; bc = 128*i + 4*lane + j; }
                }
            }
#pragma unroll
        for (int off = 16; off > 0; off >>= 1) {
            float ov = __shfl_xor_sync(0xffffffffu, bv, off);
            int   oc = __shfl_xor_sync(0xffffffffu, bc, off);
            if (ov > bv || (ov == bv && oc < bc)) { bv = ov; bc = oc; }
        }
        tv[k] = bv; tc[k] = bc;
        if (((bc >> 2) & 31) == lane) {
            int i = bc >> 7, j = bc & 3;
            sel |= 1u << (i * 4 + j);
        }
    }
    if (lane == 0) {
        float4 lp;
        lp.x = -L;
        lp.y = __fadd_rn(__fadd_rn(tv[1], -M), -L);
        lp.z = __fadd_rn(__fadd_rn(tv[2], -M), -L);
        lp.w = __fadd_rn(__fadd_rn(tv[3], -M), -L);
        g_lp4[gwarp] = lp;
        g_c4[gwarp]  = make_int4(tc[0], tc[1], tc[2], tc[3]);
        g_m[gwarp]   = make_float2(-L, __int_as_float(c1 | (1 << 30)));
    }
}

// ---------------------------------------------------------------------------
// Kernel B: one block (256 thr) per batch.
//  stage -> tie bitmask via ballots -> thread-0 chain with REGISTER-BATCHED
//  shared loads (loads hoisted out of the FADD dependence chain) storing
//  prefix only at rare tie positions -> parallel tie fixup -> warp-0 collapse.
// ---------------------------------------------------------------------------
__global__ __launch_bounds__(256) void scan_decode_kernel(float* __restrict__ out_f,
                                                          int* __restrict__ out_i,
                                                          int mode) {
    int b    = blockIdx.x;
    int tid  = threadIdx.x;
    int lane = tid & 31;
    int warp = tid >> 5;

    __shared__ float    s_lp[TT];
    __shared__ int      s_cls[TT];
    __shared__ float    s_pref[TT];     // written only at tie positions
    __shared__ unsigned s_tiem[TT / 32];
    __shared__ float    s_score;

    // stage + tie-mask build + prefill output row with -1
#pragma unroll
    for (int k = 0; k < TT / 256; k++) {
        int t = tid + 256 * k;
        float2 mrec = g_m[b * TT + t];
        int cls = __float_as_int(mrec.y);
        s_lp[t]  = mrec.x;
        s_cls[t] = cls;
        unsigned tm = __ballot_sync(0xffffffffu, (cls & (1 << 30)) != 0);
        if (lane == 0) s_tiem[8 * k + warp] = tm;
        if (mode == 0) out_f[b * TT + t] = -1.0f;
        else           out_i[b * TT + t] = -1;
    }
    __syncthreads();

    // sequential fp32 prefix chain, loads batched ahead of the FADD chain
    if (tid == 0) {
        float s = 0.0f;
        for (int blk = 0; blk < TT; blk += 32) {
            float v[32];
            const float4* lp4 = reinterpret_cast<const float4*>(s_lp + blk);
#pragma unroll
            for (int q = 0; q < 8; q++) {
                float4 f = lp4[q];
                v[4*q+0] = f.x; v[4*q+1] = f.y; v[4*q+2] = f.z; v[4*q+3] = f.w;
            }
            unsigned tm = s_tiem[blk >> 5];
            if (tm == 0u) {
#pragma unroll
                for (int j = 0; j < 32; j++) s = __fadd_rn(s, v[j]);
            } else {
#pragma unroll
                for (int j = 0; j < 32; j++) {
                    if (tm & (1u << j)) s_pref[blk + j] = s;
                    s = __fadd_rn(s, v[j]);
                }
            }
        }
        s_score = s;
    }
    __syncthreads();

    // tie resolution (parallel; flagged rows rare)
#pragma unroll
    for (int k = 0; k < TT / 256; k++) {
        int t = tid + 256 * k;
        int v = s_cls[t];
        if (v & (1 << 30)) {
            float4 lp = g_lp4[b * TT + t];
            int4   cc = g_c4[b * TT + t];
            float  s  = s_pref[t];
            float  r  = __fadd_rn(s, lp.x);
            int ch = cc.x;
            if (__fadd_rn(s, lp.y) == r && cc.y < ch) ch = cc.y;
            if (__fadd_rn(s, lp.z) == r && cc.z < ch) ch = cc.z;
            if (__fadd_rn(s, lp.w) == r && cc.w < ch) ch = cc.w;
            s_cls[t] = ch;
        }
    }
    __syncthreads();

    // warp 0: ballot CTC collapse over shared classes
    if (tid < 32) {
        int carryCnt  = 0;
        int carryPrev = -1;
        unsigned lmask = (lane == 0) ? 0u : (0xffffffffu >> (32 - lane));
        for (int chunk = 0; chunk < TT / 32; chunk++) {
            int t   = chunk * 32 + lane;
            int cls = s_cls[t];
            bool nb = (cls != 0);

            unsigned nbm   = __ballot_sync(0xffffffffu, nb);
            unsigned below = nbm & lmask;
            int src = 31 - __clz(below);
            int pc  = __shfl_sync(0xffffffffu, cls, src & 31);
            int myPrev = below ? pc : carryPrev;

            bool keep = nb && (cls != myPrev);
            unsigned km = __ballot_sync(0xffffffffu, keep);
            int dst = carryCnt + __popc(km & lmask);
            if (keep) {
                if (mode == 0) out_f[b * TT + dst] = (float)cls;
                else           out_i[b * TT + dst] = cls;
            }
            carryCnt += __popc(km);
            if (nbm) carryPrev = __shfl_sync(0xffffffffu, cls, 31 - __clz(nbm));
        }
        if (lane == 0 && mode == 0) {
            out_f[BB * TT + b]      = (float)carryCnt;  // lengths
            out_f[BB * TT + BB + b] = s_score;          // scores[:,0]
        }
    }
}

extern "C" void kernel_launch(void* const* d_in, const int* in_sizes, int n_in,
                              void* d_out, int out_size) {
    const float* logits = (const float*)d_in[0];

    row_kernel<<<(BB * TT) / 8, 256>>>(logits);

    int mode = (out_size == BB * TT) ? 1 : 0;
    scan_decode_kernel<<<BB, 256>>>((float*)d_out, (int*)d_out, mode);
}